// round 13
// baseline (speedup 1.0000x reference)
#include <cuda_runtime.h>
#include <cuda_fp16.h>
#include <cstdint>

// ============================================================================
// GroupFC: out[32768,1024] = data @ W^T + b (fp32), sm_103-compatible.
// R13: fp16 m16n8k16 GEMM with FUSED A conversion (prep_A eliminated):
//  - A read as raw fp32 via LDG.128 (prefetch distance 2 chunks), converted
//    RN to fp16 in-register, STS.128 into the swizzled stage. A crosses DRAM
//    once instead of three times (-27us prep pass).
//  - B via cp.async from g_Wh (fp16 RN pre-rounded, tiny prep kept).
//  - R12 geometry: KC=32 (64B rows), NST=3, 16KB stages, conflict-free LDS.64
//    fragment feed, sigma k-order, wait_group 1, 2 CTAs/SM.
// ============================================================================

#define BATCH   32768
#define IN_DIM  1024
#define OUT_DIM 1024

#define BM 128
#define BN 128
#define KC 32                           // fp16 k per chunk (64 B per row)
#define NCHUNK (IN_DIM / KC)            // 32
#define NST 3

#define ROW_B       64
#define TILE_BYTES  (128 * ROW_B)       // 8192
#define STAGE_BYTES (2 * TILE_BYTES)    // 16384 (A tile + B tile)
#define SMEM_TOTAL  (NST * STAGE_BYTES) // 49152

// W in fp16 (RN-rounded), static device scratch
__device__ __half g_Wh[(size_t)OUT_DIM * IN_DIM];  // 2 MB

// ---------------------------------------------------------------- helpers
__device__ __forceinline__ void cp16(uint32_t dst, const void* src) {
    asm volatile("cp.async.cg.shared.global [%0], [%1], 16;"
                 :: "r"(dst), "l"(src));
}
#define CP_COMMIT() asm volatile("cp.async.commit_group;" ::: "memory")
#define CP_WAIT_1() asm volatile("cp.async.wait_group 1;" ::: "memory")

__device__ __forceinline__ uint32_t smem_u32(const void* p) {
    uint32_t a;
    asm("{ .reg .u64 t; cvta.to.shared.u64 t, %1; cvt.u32.u64 %0, t; }"
        : "=r"(a) : "l"(p));
    return a;
}

__device__ __forceinline__ void mma16(float* c,
                                      uint32_t a0, uint32_t a1, uint32_t a2, uint32_t a3,
                                      uint32_t b0, uint32_t b1) {
    asm volatile(
        "mma.sync.aligned.m16n8k16.row.col.f32.f16.f16.f32 "
        "{%0,%1,%2,%3}, {%4,%5,%6,%7}, {%8,%9}, {%0,%1,%2,%3};"
        : "+f"(c[0]), "+f"(c[1]), "+f"(c[2]), "+f"(c[3])
        : "r"(a0), "r"(a1), "r"(a2), "r"(a3), "r"(b0), "r"(b1));
}

// two float4 (8 fp32) -> uint4 of 8 fp16 (RN)
__device__ __forceinline__ uint4 cvt8pair(float4 v0, float4 v1) {
    __half2 h0 = __float22half2_rn(make_float2(v0.x, v0.y));
    __half2 h1 = __float22half2_rn(make_float2(v0.z, v0.w));
    __half2 h2 = __float22half2_rn(make_float2(v1.x, v1.y));
    __half2 h3 = __float22half2_rn(make_float2(v1.z, v1.w));
    uint4 o;
    o.x = *reinterpret_cast<uint32_t*>(&h0);
    o.y = *reinterpret_cast<uint32_t*>(&h1);
    o.z = *reinterpret_cast<uint32_t*>(&h2);
    o.w = *reinterpret_cast<uint32_t*>(&h3);
    return o;
}

// ---------------------------------------------------------------- W prep
__global__ void __launch_bounds__(256) prep_W_kernel(const float4* __restrict__ src) {
    const size_t i8 = (size_t)blockIdx.x * blockDim.x + threadIdx.x;
    float4 v0 = src[i8 * 2];
    float4 v1 = src[i8 * 2 + 1];
    reinterpret_cast<uint4*>(g_Wh)[i8] = cvt8pair(v0, v1);
}

// ---------------------------------------------------------------- GEMM
// grid = 256 * 8 = 2048 CTAs, 128 threads. nt inner: 8 CTAs share an A stripe.
extern "C" __global__ void __launch_bounds__(128, 2)
groupfc_f16_kernel(const float* __restrict__ A, const float* __restrict__ bias,
                   float* __restrict__ out) {
    extern __shared__ char smem[];
    const uint32_t sb = smem_u32(smem);

    const int tid  = threadIdx.x;
    const int wid  = tid >> 5;
    const int lane = tid & 31;
    const int g    = lane >> 2;
    const int t    = lane & 3;
    const int wm   = wid >> 1;
    const int wn   = wid & 1;

    const int mt = blockIdx.x >> 3;
    const int nt = blockIdx.x & 7;
    const int m0 = mt * BM;
    const int n0 = nt * BN;

    // staging geometry: 128 rows x 64B tiles; thread owns 16B unit eu of rows
    // erow + 32i (i<4). Swizzle: unit u of row r at col u ^ (r&3).
    const int erow = tid >> 2;          // 0..31
    const int eu   = tid & 3;
    const uint32_t swz = (uint32_t)((eu ^ (erow & 3)) << 4);
    // A fp32 source: unit eu covers fp16 k [eu*8, eu*8+8) -> fp32 floats same idx
    const float* gAf = A + (size_t)(m0 + erow) * IN_DIM + eu * 8;
    const __half* gW = g_Wh + (size_t)(n0 + erow) * IN_DIM + eu * 8;
    const uint32_t sdA = sb + (uint32_t)erow * ROW_B + swz;
    const uint32_t sdB = sdA + TILE_BYTES;

    float c[4][8][4];
#pragma unroll
    for (int mi = 0; mi < 4; mi++)
#pragma unroll
        for (int ni = 0; ni < 8; ni++)
#pragma unroll
            for (int j = 0; j < 4; j++) c[mi][ni][j] = 0.0f;

    float4 f[8];   // in-flight fp32 A (8 float4 = 4 rows x 32B)

    // LDG A for chunk cc into f[] (always in-bounds; caller clamps cc)
#define LDGA(cc)                                                              \
    do {                                                                      \
        const float4* _p = reinterpret_cast<const float4*>(gAf + (size_t)(cc) * KC); \
        _Pragma("unroll")                                                     \
        for (int _i = 0; _i < 4; _i++) {                                      \
            f[2 * _i]     = __ldg(_p + (size_t)_i * 32 * (IN_DIM / 4));       \
            f[2 * _i + 1] = __ldg(_p + (size_t)_i * 32 * (IN_DIM / 4) + 1);   \
        }                                                                     \
    } while (0)

    // convert f[] and store into A stage s
#define CVTSTS(s)                                                             \
    do {                                                                      \
        const uint32_t _o = sdA + (uint32_t)(s) * STAGE_BYTES;                \
        _Pragma("unroll")                                                     \
        for (int _i = 0; _i < 4; _i++) {                                      \
            uint4 _h = cvt8pair(f[2 * _i], f[2 * _i + 1]);                    \
            uint32_t _ad = _o + _i * 32 * ROW_B;                              \
            asm volatile("st.shared.v4.b32 [%0], {%1,%2,%3,%4};"              \
                         :: "r"(_ad), "r"(_h.x), "r"(_h.y), "r"(_h.z), "r"(_h.w)); \
        }                                                                     \
    } while (0)

#define FILLB(cc, s)                                                          \
    do {                                                                      \
        const uint32_t _o = sdB + (uint32_t)(s) * STAGE_BYTES;                \
        const __half* _pw = gW + (size_t)(cc) * KC;                           \
        _Pragma("unroll")                                                     \
        for (int _i = 0; _i < 4; _i++)                                        \
            cp16(_o + _i * 32 * ROW_B, _pw + (size_t)_i * 32 * IN_DIM);       \
    } while (0)

    // ---- prologue: stage chunks 0 and 1
    LDGA(0); CVTSTS(0); FILLB(0, 0); CP_COMMIT();
    LDGA(1); CVTSTS(1); FILLB(1, 1); CP_COMMIT();

    const int arow0 = wm * 64 + g;
    const int brow0 = wn * 64 + g;

#pragma unroll 1
    for (int cc = 0; cc < NCHUNK; cc++) {
        CP_WAIT_1();
        __syncthreads();

        // prefetch fp32 A for chunk cc+2 (clamped; LDG lands during compute)
        const int pf = (cc + 2 < NCHUNK) ? (cc + 2) : (NCHUNK - 1);
        LDGA(pf);

        const int s = cc % NST;
        const char* pa = smem + (size_t)s * STAGE_BYTES;
        const char* pb = pa + TILE_BYTES;

#pragma unroll
        for (int ks = 0; ks < 2; ks++) {
            // sigma: thread t owns phys fp16 k {16ks+4t..16ks+4t+3} (8B unit)
            const int xsw = (((2 * ks + (t >> 1)) ^ (g & 3)) << 4) + ((t & 1) << 3);

            uint2 b[8];
#pragma unroll
            for (int ni = 0; ni < 8; ni++)
                b[ni] = *(const uint2*)(pb + (size_t)(brow0 + ni * 8) * ROW_B + xsw);

#pragma unroll
            for (int mi = 0; mi < 4; mi++) {
                const char* r0 = pa + (size_t)(arow0 + mi * 16) * ROW_B + xsw;
                uint2 lo = *(const uint2*)(r0);                 // row g:   a0, a2
                uint2 hi = *(const uint2*)(r0 + 8 * ROW_B);     // row g+8: a1, a3
#pragma unroll
                for (int ni = 0; ni < 8; ni++)
                    mma16(c[mi][ni], lo.x, hi.x, lo.y, hi.y, b[ni].x, b[ni].y);
            }
        }

        if (cc + 2 < NCHUNK) {
            const int s2 = (cc + 2) % NST;
            CVTSTS(s2);            // stage was fully read at chunk cc-1; safe
            FILLB(cc + 2, s2);
        }
        CP_COMMIT();
    }

    // ---- epilogue: bias add + float2 stores
#pragma unroll
    for (int mi = 0; mi < 4; mi++) {
        const int r = m0 + wm * 64 + mi * 16 + g;
        float* o0 = out + (size_t)r * OUT_DIM + n0 + wn * 64 + 2 * t;
        float* o1 = o0 + 8 * OUT_DIM;
#pragma unroll
        for (int ni = 0; ni < 8; ni++) {
            const int col = n0 + wn * 64 + ni * 8 + 2 * t;
            const float b0v = __ldg(bias + col);
            const float b1v = __ldg(bias + col + 1);
            *(float2*)(o0 + ni * 8) = make_float2(c[mi][ni][0] + b0v, c[mi][ni][1] + b1v);
            *(float2*)(o1 + ni * 8) = make_float2(c[mi][ni][2] + b0v, c[mi][ni][3] + b1v);
        }
    }
}

// ---------------------------------------------------------------- launch
extern "C" void kernel_launch(void* const* d_in, const int* in_sizes, int n_in,
                              void* d_out, int out_size) {
    const float* A    = (const float*)d_in[0];
    const float* W    = (const float*)d_in[1];
    const float* bias = (const float*)d_in[2];
    float* out = (float*)d_out;
    (void)in_sizes; (void)n_in; (void)out_size;

    cudaFuncSetAttribute(groupfc_f16_kernel,
                         cudaFuncAttributeMaxDynamicSharedMemorySize, SMEM_TOTAL);

    prep_W_kernel<<<512, 256>>>(reinterpret_cast<const float4*>(W));

    const int grid = (BATCH / BM) * (OUT_DIM / BN);  // 2048
    groupfc_f16_kernel<<<grid, 128, SMEM_TOTAL>>>(A, bias, out);
}

// round 14
// speedup vs baseline: 1.5244x; 1.5244x over previous
#include <cuda_runtime.h>
#include <cuda_fp16.h>
#include <cstdint>

// ============================================================================
// GroupFC: out[32768,1024] = data @ W^T + b (fp32), sm_103-compatible.
// R14: R11 split-prep fp16 m16n8k16 GEMM + ldmatrix.m8n8.x4 fragment feeding.
//  - prep_A / prep_W: fp32 -> fp16 RN (DRAM-roofline passes, 27us + 1.5us).
//  - GEMM: KC=64 (128B rows), NST=3, 96KB smem, 2 CTAs/SM, wait_group 1.
//  - swizzle: 16B unit u of row r at u ^ (r&7) -> conflict-free for both
//    cp.async row-stores and ldmatrix 8-row gathers.
//  - feed: 8 LDSM.x4 per warp-kslice-group (4 A + 4 B) vs 16 LDS.64 before.
//  - identity k-order on both operands (ldmatrix canonical quad layout).
// ============================================================================

#define BATCH   32768
#define IN_DIM  1024
#define OUT_DIM 1024

#define BM 128
#define BN 128
#define KC 64                           // fp16 k per chunk (128 B per row)
#define NCHUNK (IN_DIM / KC)            // 16
#define NST 3

#define ROW_B       128
#define TILE_BYTES  (128 * ROW_B)       // 16384
#define STAGE_BYTES (2 * TILE_BYTES)    // A tile + B tile
#define SMEM_TOTAL  (NST * STAGE_BYTES) // 98304 -> 2 CTAs/SM

// fp16 copies (RN-rounded), static device scratch
__device__ __half g_Ah[(size_t)BATCH * IN_DIM];    // 64 MB
__device__ __half g_Wh[(size_t)OUT_DIM * IN_DIM];  // 2 MB

// ---------------------------------------------------------------- helpers
__device__ __forceinline__ void cp16(uint32_t dst, const void* src) {
    asm volatile("cp.async.cg.shared.global [%0], [%1], 16;"
                 :: "r"(dst), "l"(src));
}
#define CP_COMMIT() asm volatile("cp.async.commit_group;" ::: "memory")
#define CP_WAIT_1() asm volatile("cp.async.wait_group 1;" ::: "memory")

__device__ __forceinline__ uint32_t smem_u32(const void* p) {
    uint32_t a;
    asm("{ .reg .u64 t; cvta.to.shared.u64 t, %1; cvt.u32.u64 %0, t; }"
        : "=r"(a) : "l"(p));
    return a;
}

#define LDSM4(r0, r1, r2, r3, addr)                                           \
    asm volatile("ldmatrix.sync.aligned.m8n8.x4.shared.b16 {%0,%1,%2,%3}, [%4];" \
                 : "=r"(r0), "=r"(r1), "=r"(r2), "=r"(r3) : "r"(addr))

__device__ __forceinline__ void mma16(float* c,
                                      uint32_t a0, uint32_t a1, uint32_t a2, uint32_t a3,
                                      uint32_t b0, uint32_t b1) {
    asm volatile(
        "mma.sync.aligned.m16n8k16.row.col.f32.f16.f16.f32 "
        "{%0,%1,%2,%3}, {%4,%5,%6,%7}, {%8,%9}, {%0,%1,%2,%3};"
        : "+f"(c[0]), "+f"(c[1]), "+f"(c[2]), "+f"(c[3])
        : "r"(a0), "r"(a1), "r"(a2), "r"(a3), "r"(b0), "r"(b1));
}

// ---------------------------------------------------------------- prep
__device__ __forceinline__ void cvt8(const float4* __restrict__ src,
                                     uint4* __restrict__ dst, size_t i8) {
    float4 v0 = src[i8 * 2];
    float4 v1 = src[i8 * 2 + 1];
    __half2 h0 = __float22half2_rn(make_float2(v0.x, v0.y));
    __half2 h1 = __float22half2_rn(make_float2(v0.z, v0.w));
    __half2 h2 = __float22half2_rn(make_float2(v1.x, v1.y));
    __half2 h3 = __float22half2_rn(make_float2(v1.z, v1.w));
    uint4 o;
    o.x = *reinterpret_cast<uint32_t*>(&h0);
    o.y = *reinterpret_cast<uint32_t*>(&h1);
    o.z = *reinterpret_cast<uint32_t*>(&h2);
    o.w = *reinterpret_cast<uint32_t*>(&h3);
    dst[i8] = o;
}

__global__ void __launch_bounds__(256) prep_A_kernel(const float4* __restrict__ src) {
    const size_t i8 = (size_t)blockIdx.x * blockDim.x + threadIdx.x;
    cvt8(src, reinterpret_cast<uint4*>(g_Ah), i8);
}
__global__ void __launch_bounds__(256) prep_W_kernel(const float4* __restrict__ src) {
    const size_t i8 = (size_t)blockIdx.x * blockDim.x + threadIdx.x;
    cvt8(src, reinterpret_cast<uint4*>(g_Wh), i8);
}

// ---------------------------------------------------------------- GEMM
// grid = 256 * 8 = 2048 CTAs, 128 threads. nt inner: 8 CTAs share an A stripe.
extern "C" __global__ void __launch_bounds__(128, 2)
groupfc_f16_kernel(const float* __restrict__ bias, float* __restrict__ out) {
    extern __shared__ char smem[];
    const uint32_t sb = smem_u32(smem);

    const int tid  = threadIdx.x;
    const int wid  = tid >> 5;
    const int lane = tid & 31;
    const int g    = lane >> 2;
    const int t    = lane & 3;
    const int wm   = wid >> 1;
    const int wn   = wid & 1;

    const int mt = blockIdx.x >> 3;
    const int nt = blockIdx.x & 7;
    const int m0 = mt * BM;
    const int n0 = nt * BN;

    // ldmatrix per-lane geometry
    const int e  = lane & 7;            // row-within-matrix
    const int q3 = (lane >> 3) & 1;
    const int q4 = (lane >> 4) & 1;
    // A: matrix bit0 (q3) -> rows+8, bit1 (q4) -> k-unit+1
    const int rA = wm * 64 + q3 * 8 + e;
    // B: matrix bit0 (q3) -> k-unit+1, bit1 (q4) -> rows+8
    const int rB = wn * 64 + q4 * 8 + e;

    // staging: thread fills 16B unit ech of rows erow+16i (i<8).
    // swizzle: unit u of row r stored at u ^ (r&7); (erow+16i)&7 == erow&7.
    const int erow = tid >> 3;          // 0..15
    const int ech  = tid & 7;
    const uint32_t swz = (uint32_t)((ech ^ (erow & 7)) << 4);
    const __half* gA = g_Ah + (size_t)(m0 + erow) * IN_DIM + ech * 8;
    const __half* gW = g_Wh + (size_t)(n0 + erow) * IN_DIM + ech * 8;
    const uint32_t sdA = sb + (uint32_t)erow * ROW_B + swz;
    const uint32_t sdB = sdA + TILE_BYTES;

    float c[4][8][4];
#pragma unroll
    for (int mi = 0; mi < 4; mi++)
#pragma unroll
        for (int ni = 0; ni < 8; ni++)
#pragma unroll
            for (int j = 0; j < 4; j++) c[mi][ni][j] = 0.0f;

#define FILL(cc, s)                                                           \
    do {                                                                      \
        const uint32_t _o = (uint32_t)(s) * STAGE_BYTES;                      \
        const __half* _pa = gA + (size_t)(cc) * KC;                           \
        const __half* _pw = gW + (size_t)(cc) * KC;                           \
        _Pragma("unroll")                                                     \
        for (int _i = 0; _i < 8; _i++) {                                      \
            cp16(sdA + _o + _i * 16 * ROW_B, _pa + (size_t)_i * 16 * IN_DIM); \
            cp16(sdB + _o + _i * 16 * ROW_B, _pw + (size_t)_i * 16 * IN_DIM); \
        }                                                                     \
    } while (0)

    FILL(0, 0); CP_COMMIT();
    FILL(1, 1); CP_COMMIT();

#pragma unroll 1
    for (int cc = 0; cc < NCHUNK; cc++) {
        CP_WAIT_1();
        __syncthreads();

        const int s = cc % NST;
        const uint32_t paA = sb + (uint32_t)s * STAGE_BYTES + (uint32_t)rA * ROW_B;
        const uint32_t paB = sb + (uint32_t)s * STAGE_BYTES + TILE_BYTES
                           + (uint32_t)rB * ROW_B;

#pragma unroll
        for (int ks = 0; ks < 4; ks++) {
            const uint32_t offA = (uint32_t)(((2 * ks + q4) ^ e) << 4);
            const uint32_t offB = (uint32_t)(((2 * ks + q3) ^ e) << 4);

            // B: 4x LDSM.x4 -> (b0,b1) for ni = 2p, 2p+1
            uint32_t bb[8][2];
#pragma unroll
            for (int p = 0; p < 4; p++)
                LDSM4(bb[2 * p][0], bb[2 * p][1], bb[2 * p + 1][0], bb[2 * p + 1][1],
                      paB + (uint32_t)p * 16 * ROW_B + offB);

#pragma unroll
            for (int mi = 0; mi < 4; mi++) {
                uint32_t a0, a1, a2, a3;
                LDSM4(a0, a1, a2, a3, paA + (uint32_t)mi * 16 * ROW_B + offA);
#pragma unroll
                for (int ni = 0; ni < 8; ni++)
                    mma16(c[mi][ni], a0, a1, a2, a3, bb[ni][0], bb[ni][1]);
            }
        }

        if (cc + 2 < NCHUNK) { FILL(cc + 2, (cc + 2) % NST); }
        CP_COMMIT();
    }

    // ---- epilogue: bias add + float2 stores (c-fragment layout unchanged)
#pragma unroll
    for (int mi = 0; mi < 4; mi++) {
        const int r = m0 + wm * 64 + mi * 16 + g;
        float* o0 = out + (size_t)r * OUT_DIM + n0 + wn * 64 + 2 * t;
        float* o1 = o0 + 8 * OUT_DIM;
#pragma unroll
        for (int ni = 0; ni < 8; ni++) {
            const int col = n0 + wn * 64 + ni * 8 + 2 * t;
            const float b0v = __ldg(bias + col);
            const float b1v = __ldg(bias + col + 1);
            *(float2*)(o0 + ni * 8) = make_float2(c[mi][ni][0] + b0v, c[mi][ni][1] + b1v);
            *(float2*)(o1 + ni * 8) = make_float2(c[mi][ni][2] + b0v, c[mi][ni][3] + b1v);
        }
    }
}

// ---------------------------------------------------------------- launch
extern "C" void kernel_launch(void* const* d_in, const int* in_sizes, int n_in,
                              void* d_out, int out_size) {
    const float* A    = (const float*)d_in[0];
    const float* W    = (const float*)d_in[1];
    const float* bias = (const float*)d_in[2];
    float* out = (float*)d_out;
    (void)in_sizes; (void)n_in; (void)out_size;

    cudaFuncSetAttribute(groupfc_f16_kernel,
                         cudaFuncAttributeMaxDynamicSharedMemorySize, SMEM_TOTAL);

    prep_A_kernel<<<16384, 256>>>(reinterpret_cast<const float4*>(A));
    prep_W_kernel<<<512, 256>>>(reinterpret_cast<const float4*>(W));

    const int grid = (BATCH / BM) * (OUT_DIM / BN);  // 2048
    groupfc_f16_kernel<<<grid, 128, SMEM_TOTAL>>>(bias, out);
}